// round 12
// baseline (speedup 1.0000x reference)
#include <cuda_runtime.h>
#include <cuda_bf16.h>

#define MM    8192
#define BSZ   16
#define HID   32
#define WIN   64
#define NNZ   131072
#define FW    512          // BSZ*HID features per node-row
#define NKCH  512          // fc1 split-K chunks
#define MPC   16           // m-rows per fc1 chunk (MM/NKCH)
#define KTOT  262144       // MM*HID

// ---------------- scratch (static device globals; no runtime alloc) -------
__device__ int   g_count[MM];
__device__ int   g_rowstart[MM + 1];
__device__ int   g_cursor[MM];
__device__ int   g_csrticket;
__device__ unsigned long long g_ecv[NNZ];   // packed (val<<32 | col*FW*4)
__device__ float g_bufA[MM * FW];           // 16 MB
__device__ float g_bufB[MM * FW];           // 16 MB
__device__ float g_stats[MM * 64];          // per-row [sum(32), sumsq(32)]
__device__ float g_stats2[64 * 64];
__device__ float g_bn[64];                  // scale[32], shift[32]
__device__ int   g_bnticket;
__device__ float g_part[NKCH * BSZ * FW];   // 16 MB fc1 split-K partials
__device__ float g_red[BSZ * 8 * FW];       // stage-1 reduced partials

// ---------------- f32x2 packed-FMA helpers (sm_103a) ----------------------
#define FMA2(d, a, b, c) asm("fma.rn.f32x2 %0, %1, %2, %3;" \
    : "=l"(d) : "l"(a), "l"(b), "l"(c))
#define PACKD(d, lo, hi) asm("mov.b64 %0, {%1, %2};" \
    : "=l"(d) : "f"(lo), "f"(hi))
#define UNPACKD(lo, hi, d) asm("mov.b64 {%0, %1}, %2;" \
    : "=f"(lo), "=f"(hi) : "l"(d))

// ================= CSR build: fused hist + scan (ticket) ==================
__global__ void k_histscan(const int* __restrict__ row) {
    int e0 = (blockIdx.x * 256 + threadIdx.x) * 4;
    int4 r = *(const int4*)(row + e0);
    atomicAdd(&g_count[r.x], 1);
    atomicAdd(&g_count[r.y], 1);
    atomicAdd(&g_count[r.z], 1);
    atomicAdd(&g_count[r.w], 1);
    __threadfence();
    __shared__ int lastFlag;
    if (threadIdx.x == 0)
        lastFlag = (atomicAdd(&g_csrticket, 1) == (int)gridDim.x - 1);
    __syncthreads();
    if (!lastFlag) return;
    int t = threadIdx.x;
    int loc[32];
    int s = 0;
#pragma unroll
    for (int i = 0; i < 32; i++) { loc[i] = g_count[t * 32 + i]; s += loc[i]; }
    __shared__ int sm[256];
    sm[t] = s;
    __syncthreads();
    for (int off = 1; off < 256; off <<= 1) {
        int v = (t >= off) ? sm[t - off] : 0;
        __syncthreads();
        sm[t] += v;
        __syncthreads();
    }
    int run = (t == 0) ? 0 : sm[t - 1];
#pragma unroll
    for (int i = 0; i < 32; i++) {
        g_rowstart[t * 32 + i] = run;
        g_cursor[t * 32 + i] = run;
        run += loc[i];
    }
    if (t == 255) g_rowstart[MM] = run;
    if (t == 0) g_csrticket = 0;       // reset for replay
}

__global__ void k_scatter(const int* __restrict__ row, const int* __restrict__ col,
                          const float* __restrict__ val) {
    int e0 = (blockIdx.x * 256 + threadIdx.x) * 4;
    int4 r = *(const int4*)(row + e0);
    int4 c = *(const int4*)(col + e0);
    float4 v = *(const float4*)(val + e0);
    // low word = col * FW * 4 (byte offset into x), so spmm does 1 add
    int p0 = atomicAdd(&g_cursor[r.x], 1);
    g_ecv[p0] = ((unsigned long long)__float_as_uint(v.x) << 32) | ((unsigned)c.x * (FW * 4u));
    int p1 = atomicAdd(&g_cursor[r.y], 1);
    g_ecv[p1] = ((unsigned long long)__float_as_uint(v.y) << 32) | ((unsigned)c.y * (FW * 4u));
    int p2 = atomicAdd(&g_cursor[r.z], 1);
    g_ecv[p2] = ((unsigned long long)__float_as_uint(v.z) << 32) | ((unsigned)c.z * (FW * 4u));
    int p3 = atomicAdd(&g_cursor[r.w], 1);
    g_ecv[p3] = ((unsigned long long)__float_as_uint(v.w) << 32) | ((unsigned)c.w * (FW * 4u));
}

// ================= layer-1 linear: bufA[(m,b),:] = inputs[b,m,:] @ W1 =====
#define L1S 68
__global__ void __launch_bounds__(256) k_lin1(const float* __restrict__ x,
                                              const float* __restrict__ W) {
    __shared__ __align__(16) float w[WIN * HID];   // 8 KB
    __shared__ __align__(16) float xs[256 * L1S];  // 68 KB
    int t = threadIdx.x;
    int m0 = blockIdx.x * 16;
    {
        const float4* Wv = (const float4*)W;
        float4* wv = (float4*)w;
#pragma unroll
        for (int p = 0; p < 2; p++) wv[t + p * 256] = Wv[t + p * 256];
    }
#pragma unroll
    for (int p = 0; p < 16; p++) {        // stage 4096 float4
        int idx = t + p * 256;
        int r = idx >> 4, f4 = idx & 15;  // r = mm*16 + b
        int b = r & 15, mm = r >> 4;
        float4 v = *(const float4*)(x + ((size_t)b * MM + m0 + mm) * WIN + f4 * 4);
        *(float4*)(xs + r * L1S + f4 * 4) = v;
    }
    __syncthreads();
    int rg = t >> 2;                      // rows 4rg .. 4rg+3
    int cg = t & 3;                       // channels cg*8 .. cg*8+7 (4 pairs)
    const float* xr = xs + (4 * rg) * L1S;
    unsigned long long acc[16];           // acc[row i][pair p] = acc[i*4+p]
#pragma unroll
    for (int i = 0; i < 16; i++) acc[i] = 0ULL;
#pragma unroll 4
    for (int k4 = 0; k4 < WIN / 4; k4++) {
        float4 xv0 = *(const float4*)(xr + 0 * L1S + k4 * 4);
        float4 xv1 = *(const float4*)(xr + 1 * L1S + k4 * 4);
        float4 xv2 = *(const float4*)(xr + 2 * L1S + k4 * 4);
        float4 xv3 = *(const float4*)(xr + 3 * L1S + k4 * 4);
#pragma unroll
        for (int kk = 0; kk < 4; kk++) {
            float e0 = (kk == 0) ? xv0.x : (kk == 1) ? xv0.y : (kk == 2) ? xv0.z : xv0.w;
            float e1 = (kk == 0) ? xv1.x : (kk == 1) ? xv1.y : (kk == 2) ? xv1.z : xv1.w;
            float e2 = (kk == 0) ? xv2.x : (kk == 1) ? xv2.y : (kk == 2) ? xv2.z : xv2.w;
            float e3 = (kk == 0) ? xv3.x : (kk == 1) ? xv3.y : (kk == 2) ? xv3.z : xv3.w;
            unsigned long long d0, d1, d2, d3;
            PACKD(d0, e0, e0); PACKD(d1, e1, e1);
            PACKD(d2, e2, e2); PACKD(d3, e3, e3);
            const ulonglong2* wr =
                (const ulonglong2*)(w + (k4 * 4 + kk) * HID + cg * 8);
            ulonglong2 wa = wr[0];
            ulonglong2 wb = wr[1];
            FMA2(acc[0 * 4 + 0], d0, wa.x, acc[0 * 4 + 0]);
            FMA2(acc[0 * 4 + 1], d0, wa.y, acc[0 * 4 + 1]);
            FMA2(acc[0 * 4 + 2], d0, wb.x, acc[0 * 4 + 2]);
            FMA2(acc[0 * 4 + 3], d0, wb.y, acc[0 * 4 + 3]);
            FMA2(acc[1 * 4 + 0], d1, wa.x, acc[1 * 4 + 0]);
            FMA2(acc[1 * 4 + 1], d1, wa.y, acc[1 * 4 + 1]);
            FMA2(acc[1 * 4 + 2], d1, wb.x, acc[1 * 4 + 2]);
            FMA2(acc[1 * 4 + 3], d1, wb.y, acc[1 * 4 + 3]);
            FMA2(acc[2 * 4 + 0], d2, wa.x, acc[2 * 4 + 0]);
            FMA2(acc[2 * 4 + 1], d2, wa.y, acc[2 * 4 + 1]);
            FMA2(acc[2 * 4 + 2], d2, wb.x, acc[2 * 4 + 2]);
            FMA2(acc[2 * 4 + 3], d2, wb.y, acc[2 * 4 + 3]);
            FMA2(acc[3 * 4 + 0], d3, wa.x, acc[3 * 4 + 0]);
            FMA2(acc[3 * 4 + 1], d3, wa.y, acc[3 * 4 + 1]);
            FMA2(acc[3 * 4 + 2], d3, wb.x, acc[3 * 4 + 2]);
            FMA2(acc[3 * 4 + 3], d3, wb.y, acc[3 * 4 + 3]);
        }
    }
#pragma unroll
    for (int i = 0; i < 4; i++) {
        int r = 4 * rg + i;
        int b = r & 15, mm = r >> 4;
        float* o = g_bufA + (((size_t)(m0 + mm) * BSZ) + b) * HID + cg * 8;
        float lo0, hi0, lo1, hi1, lo2, hi2, lo3, hi3;
        UNPACKD(lo0, hi0, acc[i * 4 + 0]);
        UNPACKD(lo1, hi1, acc[i * 4 + 1]);
        UNPACKD(lo2, hi2, acc[i * 4 + 2]);
        UNPACKD(lo3, hi3, acc[i * 4 + 3]);
        float4 v0 = {lo0, hi0, lo1, hi1};
        float4 v1 = {lo2, hi2, lo3, hi3};
        *(float4*)(o + 0) = v0;
        *(float4*)(o + 4) = v1;
    }
}

// ================= SpMM: y[r,:] = sum_e val*x[col,:] + bias; + BN partials =
// No smem staging: edge words are uniform-address loads (1 sector, L1-hot);
// 4 gathers in flight per thread.
__global__ void k_spmm(const float* __restrict__ x, const float* __restrict__ bias,
                       float* __restrict__ y) {
    int r = blockIdx.x;
    int t = threadIdx.x;                 // 128 threads, 4 features each
    __shared__ float4 ssum[128];
    __shared__ float4 ssq[128];
    int s = g_rowstart[r], e = g_rowstart[r + 1];
    const char* xb = (const char*)x + (size_t)t * 16;   // per-thread byte base
    float4 a0 = {0,0,0,0}, a1 = {0,0,0,0}, a2 = {0,0,0,0}, a3 = {0,0,0,0};
    int i = s;
    for (; i + 4 <= e; i += 4) {
        unsigned long long u0 = __ldg(&g_ecv[i + 0]);
        unsigned long long u1 = __ldg(&g_ecv[i + 1]);
        unsigned long long u2 = __ldg(&g_ecv[i + 2]);
        unsigned long long u3 = __ldg(&g_ecv[i + 3]);
        float v0 = __uint_as_float((unsigned)(u0 >> 32));
        float v1 = __uint_as_float((unsigned)(u1 >> 32));
        float v2 = __uint_as_float((unsigned)(u2 >> 32));
        float v3 = __uint_as_float((unsigned)(u3 >> 32));
        float4 x0 = *(const float4*)(xb + (unsigned)u0);
        float4 x1 = *(const float4*)(xb + (unsigned)u1);
        float4 x2 = *(const float4*)(xb + (unsigned)u2);
        float4 x3 = *(const float4*)(xb + (unsigned)u3);
        a0.x += v0 * x0.x; a0.y += v0 * x0.y; a0.z += v0 * x0.z; a0.w += v0 * x0.w;
        a1.x += v1 * x1.x; a1.y += v1 * x1.y; a1.z += v1 * x1.z; a1.w += v1 * x1.w;
        a2.x += v2 * x2.x; a2.y += v2 * x2.y; a2.z += v2 * x2.z; a2.w += v2 * x2.w;
        a3.x += v3 * x3.x; a3.y += v3 * x3.y; a3.z += v3 * x3.z; a3.w += v3 * x3.w;
    }
    for (; i < e; i++) {
        unsigned long long u = __ldg(&g_ecv[i]);
        float v = __uint_as_float((unsigned)(u >> 32));
        float4 xv = *(const float4*)(xb + (unsigned)u);
        a0.x += v * xv.x; a0.y += v * xv.y; a0.z += v * xv.z; a0.w += v * xv.w;
    }
    float4 acc;
    acc.x = (a0.x + a1.x) + (a2.x + a3.x);
    acc.y = (a0.y + a1.y) + (a2.y + a3.y);
    acc.z = (a0.z + a1.z) + (a2.z + a3.z);
    acc.w = (a0.w + a1.w) + (a2.w + a3.w);
    int c0 = (t & 7) * 4;                // channel base (feature = b*32+c)
    float4 bv = *(const float4*)(bias + c0);
    acc.x += bv.x; acc.y += bv.y; acc.z += bv.z; acc.w += bv.w;
    *(float4*)(y + (size_t)r * FW + t * 4) = acc;
    ssum[t] = acc;
    float4 sq = {acc.x * acc.x, acc.y * acc.y, acc.z * acc.z, acc.w * acc.w};
    ssq[t] = sq;
    __syncthreads();
    if (t < 8) {                         // deterministic reduce over 16 b
        float4 a = {0, 0, 0, 0}, q = {0, 0, 0, 0};
        for (int k = 0; k < 16; k++) {
            float4 u = ssum[k * 8 + t], v = ssq[k * 8 + t];
            a.x += u.x; a.y += u.y; a.z += u.z; a.w += u.w;
            q.x += v.x; q.y += v.y; q.z += v.z; q.w += v.w;
        }
        *(float4*)(g_stats + (size_t)r * 64 + t * 4) = a;
        *(float4*)(g_stats + (size_t)r * 64 + 32 + t * 4) = q;
    }
}

// ================= fused BN reduction (ticket / last-block) ===============
__global__ void k_bn(const float* __restrict__ g, const float* __restrict__ be) {
    int bx = blockIdx.x, t = threadIdx.x;      // grid 64, 256 threads
    int col = t & 63, seg = t >> 6;            // 4 segments x 32 rows
    float s = 0.f;
    int r0 = bx * 128 + seg * 32;
    for (int i = 0; i < 32; i++) s += g_stats[(size_t)(r0 + i) * 64 + col];
    __shared__ float sm[256];
    sm[t] = s;
    __syncthreads();
    if (seg == 0)
        g_stats2[bx * 64 + col] = sm[col] + sm[64 + col] + sm[128 + col] + sm[192 + col];
    __threadfence();
    __shared__ int lastFlag;
    if (t == 0) lastFlag = (atomicAdd(&g_bnticket, 1) == 63);
    __syncthreads();
    if (lastFlag) {
        if (t < 64) {
            float ss = 0.f;
            for (int i = 0; i < 64; i++) ss += g_stats2[i * 64 + t];
            sm[t] = ss;
        }
        __syncthreads();
        if (t < 32) {
            const float inv_n = 1.f / (float)(BSZ * MM);
            float mean = sm[t] * inv_n;
            float var = sm[32 + t] * inv_n - mean * mean;
            float sc = g[t] * rsqrtf(var + 1e-5f);
            g_bn[t] = sc;
            g_bn[32 + t] = be[t] - mean * sc;
        }
        if (t == 0) g_bnticket = 0;   // reset for next use / replay
    }
}

// ================= layer-2 linear, staged + f32x2, fused BN+ReLU ==========
#define L2S 36
__global__ void __launch_bounds__(256) k_lin2(const float* __restrict__ y,
                                              const float* __restrict__ W,
                                              float* __restrict__ out) {
    __shared__ __align__(16) float w[HID * HID];   // 4 KB
    __shared__ __align__(16) float xs[256 * L2S];  // 36 KB
    __shared__ __align__(16) float sc[32], sh[32];
    int t = threadIdx.x;
    {
        const float4* Wv = (const float4*)W;
        float4* wv = (float4*)w;
        if (t < 256) wv[t] = Wv[t];
    }
    if (t < 32) { sc[t] = g_bn[t]; sh[t] = g_bn[32 + t]; }
    __syncthreads();
    int r0 = blockIdx.x * 256;
#pragma unroll
    for (int p = 0; p < 8; p++) {          // stage 2048 float4 with BN+ReLU
        int idx = t + p * 256;
        int r = idx >> 3, f4 = idx & 7;
        float4 v = *(const float4*)(y + ((size_t)(r0 + r)) * HID + f4 * 4);
        float4 s4 = *(const float4*)(sc + f4 * 4);
        float4 h4 = *(const float4*)(sh + f4 * 4);
        float4 o;
        o.x = fmaxf(s4.x * v.x + h4.x, 0.f);
        o.y = fmaxf(s4.y * v.y + h4.y, 0.f);
        o.z = fmaxf(s4.z * v.z + h4.z, 0.f);
        o.w = fmaxf(s4.w * v.w + h4.w, 0.f);
        *(float4*)(xs + r * L2S + f4 * 4) = o;
    }
    __syncthreads();
    int rp = t >> 1;
    int h = t & 1;
    const float* xr0 = xs + (2 * rp) * L2S;
    const float* xr1 = xr0 + L2S;
    unsigned long long acc0[8], acc1[8];
#pragma unroll
    for (int i = 0; i < 8; i++) { acc0[i] = 0ULL; acc1[i] = 0ULL; }
#pragma unroll
    for (int k4 = 0; k4 < HID / 4; k4++) {
        float4 xa = *(const float4*)(xr0 + k4 * 4);
        float4 xb = *(const float4*)(xr1 + k4 * 4);
#pragma unroll
        for (int kk = 0; kk < 4; kk++) {
            float e0 = (kk == 0) ? xa.x : (kk == 1) ? xa.y : (kk == 2) ? xa.z : xa.w;
            float e1 = (kk == 0) ? xb.x : (kk == 1) ? xb.y : (kk == 2) ? xb.z : xb.w;
            unsigned long long d0, d1;
            PACKD(d0, e0, e0); PACKD(d1, e1, e1);
            const ulonglong2* wr = (const ulonglong2*)(w + (k4 * 4 + kk) * HID + h * 16);
#pragma unroll
            for (int q = 0; q < 4; q++) {
                ulonglong2 wp = wr[q];
                FMA2(acc0[2 * q + 0], d0, wp.x, acc0[2 * q + 0]);
                FMA2(acc0[2 * q + 1], d0, wp.y, acc0[2 * q + 1]);
                FMA2(acc1[2 * q + 0], d1, wp.x, acc1[2 * q + 0]);
                FMA2(acc1[2 * q + 1], d1, wp.y, acc1[2 * q + 1]);
            }
        }
    }
    float* o0 = out + ((size_t)(r0 + 2 * rp)) * HID + h * 16;
    float* o1 = o0 + HID;
#pragma unroll
    for (int q = 0; q < 4; q++) {
        float lo0, hi0, lo1, hi1;
        UNPACKD(lo0, hi0, acc0[2 * q + 0]);
        UNPACKD(lo1, hi1, acc0[2 * q + 1]);
        float4 v = {lo0, hi0, lo1, hi1};
        *(float4*)(o0 + q * 4) = v;
    }
#pragma unroll
    for (int q = 0; q < 4; q++) {
        float lo0, hi0, lo1, hi1;
        UNPACKD(lo0, hi0, acc1[2 * q + 0]);
        UNPACKD(lo1, hi1, acc1[2 * q + 1]);
        float4 v = {lo0, hi0, lo1, hi1};
        *(float4*)(o1 + q * 4) = v;
    }
}

// ================= fc1 split-K GEMM: 256 thr, j-pair, depth-4 prefetch ====
// Thread owns j-pair (j0 = t*2); all 512 j covered once per block, w element
// loaded exactly once. 32 warps/SM for HBM latency coverage.
#define FC1_STEP(F, KCC) do {                                               \
    unsigned long long w2x, w2y;                                            \
    PACKD(w2x, (F).x, (F).x);                                               \
    PACKD(w2y, (F).y, (F).y);                                               \
    const ulonglong2* xp = (const ulonglong2*)(xs + (KCC) * 16);            \
    ulonglong2 xA = xp[0], xB = xp[1], xC = xp[2], xD = xp[3];              \
    unsigned long long xv[8] = {xA.x, xA.y, xB.x, xB.y,                     \
                                xC.x, xC.y, xD.x, xD.y};                    \
    _Pragma("unroll")                                                       \
    for (int bp = 0; bp < 8; bp++) {                                        \
        FMA2(acc[0 * 8 + bp], xv[bp], w2x, acc[0 * 8 + bp]);                \
        FMA2(acc[1 * 8 + bp], xv[bp], w2y, acc[1 * 8 + bp]);                \
    }                                                                       \
} while (0)

__global__ void __launch_bounds__(256) k_fc1(const float* __restrict__ w,
                                             const float* __restrict__ y2) {
    int ck = blockIdx.x;                  // K-chunk: m in [ck*16, ck*16+16)
    int t = threadIdx.x;                  // 256
    __shared__ __align__(16) float xs[MPC * HID * 16];  // 32.8 KB, stride 16
    __shared__ float sc[32], sh[32];
    if (t < 32) { sc[t] = g_bn[t]; sh[t] = g_bn[32 + t]; }
    __syncthreads();
    {   // stage 16 rows (2048 float4 over 256 threads = 8 iters)
        int c0 = (t & 7) * 4;             // idx&127 == t&127, so c0 fixed
        int b = (t & 127) >> 3;
        float s0 = sc[c0 + 0], s1 = sc[c0 + 1], s2 = sc[c0 + 2], s3 = sc[c0 + 3];
        float h0 = sh[c0 + 0], h1 = sh[c0 + 1], h2 = sh[c0 + 2], h3 = sh[c0 + 3];
#pragma unroll
        for (int p = 0; p < 8; p++) {
            int idx = t + p * 256;
            int mi = idx >> 7;            // 0..15
            int q = idx & 127;
            float4 v = *(const float4*)(y2 + ((size_t)(ck * MPC + mi)) * FW + q * 4);
            float* xr = xs + (mi * HID + c0) * 16;
            xr[b]      = fmaxf(s0 * v.x + h0, 0.f);
            xr[16 + b] = fmaxf(s1 * v.y + h1, 0.f);
            xr[32 + b] = fmaxf(s2 * v.z + h2, 0.f);
            xr[48 + b] = fmaxf(s3 * v.w + h3, 0.f);
        }
    }
    __syncthreads();
    unsigned long long acc[16];           // acc[j(2)][b-pair(8)]
#pragma unroll
    for (int i = 0; i < 16; i++) acc[i] = 0ULL;
    int j0 = t * 2;
    const float* wp = w + (size_t)ck * (MPC * HID) * FW + j0;
    // depth-4 rolling prefetch (LDG.64); reads up to 3 rows past the chunk,
    // safe: w has KTOT+32 rows, last chunk ends 31 rows before the end.
    float2 f0 = *(const float2*)(wp + 0 * FW);
    float2 f1 = *(const float2*)(wp + 1 * FW);
    float2 f2 = *(const float2*)(wp + 2 * FW);
    float2 f3 = *(const float2*)(wp + 3 * FW);
#pragma unroll 1
    for (int kc = 0; kc < MPC * HID - 4; kc += 4) {
        float2 n0 = *(const float2*)(wp + (size_t)(kc + 4) * FW);
        float2 n1 = *(const float2*)(wp + (size_t)(kc + 5) * FW);
        float2 n2 = *(const float2*)(wp + (size_t)(kc + 6) * FW);
        float2 n3 = *(const float2*)(wp + (size_t)(kc + 7) * FW);
        FC1_STEP(f0, kc + 0);
        FC1_STEP(f1, kc + 1);
        FC1_STEP(f2, kc + 2);
        FC1_STEP(f3, kc + 3);
        f0 = n0; f1 = n1; f2 = n2; f3 = n3;
    }
    FC1_STEP(f0, MPC * HID - 4);
    FC1_STEP(f1, MPC * HID - 3);
    FC1_STEP(f2, MPC * HID - 2);
    FC1_STEP(f3, MPC * HID - 1);
    float* pbase = g_part + (size_t)ck * BSZ * FW + j0;
#pragma unroll
    for (int bp = 0; bp < 8; bp++) {      // b-pair bp -> rows 2bp, 2bp+1
        float lo0, hi0, lo1, hi1;
        UNPACKD(lo0, hi0, acc[0 * 8 + bp]);
        UNPACKD(lo1, hi1, acc[1 * 8 + bp]);
        float2 ev = {lo0, lo1};
        float2 ov = {hi0, hi1};
        *(float2*)(pbase + (size_t)(2 * bp + 0) * FW) = ev;
        *(float2*)(pbase + (size_t)(2 * bp + 1) * FW) = ov;
    }
}

// ================= reduce partials (stage 1, coalesced float4) ============
__global__ void k_red1() {
    int b = blockIdx.x >> 3;             // 0..15
    int grp = blockIdx.x & 7;            // 0..7, each covers 64 chunks
    int t = threadIdx.x;                 // 128 threads, j-quad each
    const float* p = g_part + (size_t)(grp * 64) * BSZ * FW + (size_t)b * FW + t * 4;
    float4 s = {0, 0, 0, 0};
#pragma unroll 8
    for (int k = 0; k < 64; k++) {
        float4 v = *(const float4*)(p + (size_t)k * BSZ * FW);
        s.x += v.x; s.y += v.y; s.z += v.z; s.w += v.w;
    }
    *(float4*)(g_red + (size_t)(b * 8 + grp) * FW + t * 4) = s;
}

// ================= final: reduce + extras + bias + relu + fc2 =============
__global__ void k_red2(const float* __restrict__ w, const float* __restrict__ fc1b,
                       const float* __restrict__ ex, const float* __restrict__ fc2w,
                       const float* __restrict__ fc2b, float* __restrict__ out) {
    int b = blockIdx.x;                  // 16 blocks
    int j = threadIdx.x;                 // 512 threads
    float acc = fc1b[j];
#pragma unroll
    for (int g = 0; g < 8; g++) acc += g_red[(size_t)(b * 8 + g) * FW + j];
#pragma unroll
    for (int e2 = 0; e2 < 32; e2++)
        acc += ex[b * 32 + e2] * w[((size_t)KTOT + e2) * FW + j];
    float h = fmaxf(acc, 0.f);
    __shared__ float r0[512], r1[512];
    r0[j] = h * fc2w[j * 2 + 0];
    r1[j] = h * fc2w[j * 2 + 1];
    __syncthreads();
    for (int s = 256; s > 0; s >>= 1) {
        if (j < s) { r0[j] += r0[j + s]; r1[j] += r1[j + s]; }
        __syncthreads();
    }
    if (j == 0) {
        out[b * 2 + 0] = r0[0] + fc2b[0];
        out[b * 2 + 1] = r1[0] + fc2b[1];
    }
}

// ================= launch ==================================================
extern "C" void kernel_launch(void* const* d_in, const int* in_sizes, int n_in,
                              void* d_out, int out_size) {
    const float* inputs  = (const float*)d_in[0];
    const float* ex      = (const float*)d_in[1];
    const int*   erow    = (const int*)  d_in[2];
    const int*   ecol    = (const int*)  d_in[3];
    const float* eval    = (const float*)d_in[4];
    const float* W1      = (const float*)d_in[5];
    const float* b1      = (const float*)d_in[6];
    const float* g1      = (const float*)d_in[7];
    const float* be1     = (const float*)d_in[8];
    const float* W2      = (const float*)d_in[9];
    const float* b2      = (const float*)d_in[10];
    const float* g2      = (const float*)d_in[11];
    const float* be2     = (const float*)d_in[12];
    const float* fc1w    = (const float*)d_in[13];
    const float* fc1b    = (const float*)d_in[14];
    const float* fc2w    = (const float*)d_in[15];
    const float* fc2b    = (const float*)d_in[16];
    float* out = (float*)d_out;

    float* bufA; cudaGetSymbolAddress((void**)&bufA, g_bufA);
    float* bufB; cudaGetSymbolAddress((void**)&bufB, g_bufB);
    int* cnt;    cudaGetSymbolAddress((void**)&cnt,  g_count);

    // Kernel order: spmm is the 4th kernel launch -> profiled by ncu.
    cudaMemsetAsync(cnt, 0, MM * sizeof(int));
    k_histscan<<<NNZ / 1024, 256>>>(erow);                  // k1: hist+scan fused
    k_lin1<<<MM / 16, 256>>>(inputs, W1);                   // k2: bufA = X@W1
    k_scatter<<<NNZ / 1024, 256>>>(erow, ecol, eval);       // k3
    k_spmm<<<MM, 128>>>(bufA, b1, bufB);                    // k4 (profiled)
    k_bn<<<64, 256>>>(g1, be1);
    k_lin2<<<(BSZ * MM) / 256, 256>>>(bufB, W2, bufA);      // bufA = bnrelu(bufB)@W2
    k_spmm<<<MM, 128>>>(bufA, b2, bufB);                    // bufB = L@bufA + b2
    k_bn<<<64, 256>>>(g2, be2);

    k_fc1<<<NKCH, 256>>>(fc1w, bufB);                       // split-K partials
    k_red1<<<BSZ * 8, 128>>>();                             // coalesced partial reduce
    k_red2<<<BSZ, 512>>>(fc1w, fc1b, ex, fc2w, fc2b, out);  // finish + fc2
}

// round 13
// speedup vs baseline: 1.3356x; 1.3356x over previous
#include <cuda_runtime.h>
#include <cuda_bf16.h>

#define MM    8192
#define BSZ   16
#define HID   32
#define WIN   64
#define NNZ   131072
#define FW    512          // BSZ*HID features per node-row
#define NKCH  512          // fc1 split-K chunks
#define MPC   16           // m-rows per fc1 chunk (MM/NKCH)
#define KTOT  262144       // MM*HID

// ---------------- scratch (static device globals; no runtime alloc) -------
__device__ int   g_count[MM];
__device__ int   g_rowstart[MM + 1];
__device__ int   g_cursor[MM];
__device__ int   g_csrticket;
__device__ unsigned long long g_ecv[NNZ];   // packed (val<<32 | col*FW*4)
__device__ float g_bufA[MM * FW];           // 16 MB
__device__ float g_bufB[MM * FW];           // 16 MB
__device__ float g_stats[MM * 64];          // per-row [sum(32), sumsq(32)]
__device__ float g_stats2[64 * 64];
__device__ float g_bn[64];                  // scale[32], shift[32]
__device__ int   g_bnticket;
__device__ float g_part[NKCH * BSZ * FW];   // 16 MB fc1 split-K partials
__device__ float g_red[BSZ * 8 * FW];       // stage-1 reduced partials

// ---------------- f32x2 packed-FMA helpers (sm_103a) ----------------------
#define FMA2(d, a, b, c) asm("fma.rn.f32x2 %0, %1, %2, %3;" \
    : "=l"(d) : "l"(a), "l"(b), "l"(c))
#define PACKD(d, lo, hi) asm("mov.b64 %0, {%1, %2};" \
    : "=l"(d) : "f"(lo), "f"(hi))
#define UNPACKD(lo, hi, d) asm("mov.b64 {%0, %1}, %2;" \
    : "=f"(lo), "=f"(hi) : "l"(d))

// ================= CSR build: fused hist + scan (ticket) ==================
__global__ void k_histscan(const int* __restrict__ row) {
    int e0 = (blockIdx.x * 256 + threadIdx.x) * 4;
    int4 r = *(const int4*)(row + e0);
    atomicAdd(&g_count[r.x], 1);
    atomicAdd(&g_count[r.y], 1);
    atomicAdd(&g_count[r.z], 1);
    atomicAdd(&g_count[r.w], 1);
    __threadfence();
    __shared__ int lastFlag;
    if (threadIdx.x == 0)
        lastFlag = (atomicAdd(&g_csrticket, 1) == (int)gridDim.x - 1);
    __syncthreads();
    if (!lastFlag) return;
    int t = threadIdx.x;
    int loc[32];
    int s = 0;
#pragma unroll
    for (int i = 0; i < 32; i++) { loc[i] = g_count[t * 32 + i]; s += loc[i]; }
    __shared__ int sm[256];
    sm[t] = s;
    __syncthreads();
    for (int off = 1; off < 256; off <<= 1) {
        int v = (t >= off) ? sm[t - off] : 0;
        __syncthreads();
        sm[t] += v;
        __syncthreads();
    }
    int run = (t == 0) ? 0 : sm[t - 1];
#pragma unroll
    for (int i = 0; i < 32; i++) {
        g_rowstart[t * 32 + i] = run;
        g_cursor[t * 32 + i] = run;
        run += loc[i];
    }
    if (t == 255) g_rowstart[MM] = run;
    if (t == 0) g_csrticket = 0;       // reset for replay
}

__global__ void k_scatter(const int* __restrict__ row, const int* __restrict__ col,
                          const float* __restrict__ val) {
    int e0 = (blockIdx.x * 256 + threadIdx.x) * 4;
    int4 r = *(const int4*)(row + e0);
    int4 c = *(const int4*)(col + e0);
    float4 v = *(const float4*)(val + e0);
    // low word = col * FW * 4 (byte offset into x), so spmm does 1 add
    int p0 = atomicAdd(&g_cursor[r.x], 1);
    g_ecv[p0] = ((unsigned long long)__float_as_uint(v.x) << 32) | ((unsigned)c.x * (FW * 4u));
    int p1 = atomicAdd(&g_cursor[r.y], 1);
    g_ecv[p1] = ((unsigned long long)__float_as_uint(v.y) << 32) | ((unsigned)c.y * (FW * 4u));
    int p2 = atomicAdd(&g_cursor[r.z], 1);
    g_ecv[p2] = ((unsigned long long)__float_as_uint(v.z) << 32) | ((unsigned)c.z * (FW * 4u));
    int p3 = atomicAdd(&g_cursor[r.w], 1);
    g_ecv[p3] = ((unsigned long long)__float_as_uint(v.w) << 32) | ((unsigned)c.w * (FW * 4u));
}

// ================= layer-1 linear: bufA[(m,b),:] = inputs[b,m,:] @ W1 =====
#define L1S 68
__global__ void __launch_bounds__(256) k_lin1(const float* __restrict__ x,
                                              const float* __restrict__ W) {
    __shared__ __align__(16) float w[WIN * HID];   // 8 KB
    __shared__ __align__(16) float xs[256 * L1S];  // 68 KB
    int t = threadIdx.x;
    int m0 = blockIdx.x * 16;
    {
        const float4* Wv = (const float4*)W;
        float4* wv = (float4*)w;
#pragma unroll
        for (int p = 0; p < 2; p++) wv[t + p * 256] = Wv[t + p * 256];
    }
#pragma unroll
    for (int p = 0; p < 16; p++) {        // stage 4096 float4
        int idx = t + p * 256;
        int r = idx >> 4, f4 = idx & 15;  // r = mm*16 + b
        int b = r & 15, mm = r >> 4;
        float4 v = *(const float4*)(x + ((size_t)b * MM + m0 + mm) * WIN + f4 * 4);
        *(float4*)(xs + r * L1S + f4 * 4) = v;
    }
    __syncthreads();
    int rg = t >> 2;                      // rows 4rg .. 4rg+3
    int cg = t & 3;                       // channels cg*8 .. cg*8+7 (4 pairs)
    const float* xr = xs + (4 * rg) * L1S;
    unsigned long long acc[16];           // acc[row i][pair p] = acc[i*4+p]
#pragma unroll
    for (int i = 0; i < 16; i++) acc[i] = 0ULL;
#pragma unroll 4
    for (int k4 = 0; k4 < WIN / 4; k4++) {
        float4 xv0 = *(const float4*)(xr + 0 * L1S + k4 * 4);
        float4 xv1 = *(const float4*)(xr + 1 * L1S + k4 * 4);
        float4 xv2 = *(const float4*)(xr + 2 * L1S + k4 * 4);
        float4 xv3 = *(const float4*)(xr + 3 * L1S + k4 * 4);
#pragma unroll
        for (int kk = 0; kk < 4; kk++) {
            float e0 = (kk == 0) ? xv0.x : (kk == 1) ? xv0.y : (kk == 2) ? xv0.z : xv0.w;
            float e1 = (kk == 0) ? xv1.x : (kk == 1) ? xv1.y : (kk == 2) ? xv1.z : xv1.w;
            float e2 = (kk == 0) ? xv2.x : (kk == 1) ? xv2.y : (kk == 2) ? xv2.z : xv2.w;
            float e3 = (kk == 0) ? xv3.x : (kk == 1) ? xv3.y : (kk == 2) ? xv3.z : xv3.w;
            unsigned long long d0, d1, d2, d3;
            PACKD(d0, e0, e0); PACKD(d1, e1, e1);
            PACKD(d2, e2, e2); PACKD(d3, e3, e3);
            const ulonglong2* wr =
                (const ulonglong2*)(w + (k4 * 4 + kk) * HID + cg * 8);
            ulonglong2 wa = wr[0];
            ulonglong2 wb = wr[1];
            FMA2(acc[0 * 4 + 0], d0, wa.x, acc[0 * 4 + 0]);
            FMA2(acc[0 * 4 + 1], d0, wa.y, acc[0 * 4 + 1]);
            FMA2(acc[0 * 4 + 2], d0, wb.x, acc[0 * 4 + 2]);
            FMA2(acc[0 * 4 + 3], d0, wb.y, acc[0 * 4 + 3]);
            FMA2(acc[1 * 4 + 0], d1, wa.x, acc[1 * 4 + 0]);
            FMA2(acc[1 * 4 + 1], d1, wa.y, acc[1 * 4 + 1]);
            FMA2(acc[1 * 4 + 2], d1, wb.x, acc[1 * 4 + 2]);
            FMA2(acc[1 * 4 + 3], d1, wb.y, acc[1 * 4 + 3]);
            FMA2(acc[2 * 4 + 0], d2, wa.x, acc[2 * 4 + 0]);
            FMA2(acc[2 * 4 + 1], d2, wa.y, acc[2 * 4 + 1]);
            FMA2(acc[2 * 4 + 2], d2, wb.x, acc[2 * 4 + 2]);
            FMA2(acc[2 * 4 + 3], d2, wb.y, acc[2 * 4 + 3]);
            FMA2(acc[3 * 4 + 0], d3, wa.x, acc[3 * 4 + 0]);
            FMA2(acc[3 * 4 + 1], d3, wa.y, acc[3 * 4 + 1]);
            FMA2(acc[3 * 4 + 2], d3, wb.x, acc[3 * 4 + 2]);
            FMA2(acc[3 * 4 + 3], d3, wb.y, acc[3 * 4 + 3]);
        }
    }
#pragma unroll
    for (int i = 0; i < 4; i++) {
        int r = 4 * rg + i;
        int b = r & 15, mm = r >> 4;
        float* o = g_bufA + (((size_t)(m0 + mm) * BSZ) + b) * HID + cg * 8;
        float lo0, hi0, lo1, hi1, lo2, hi2, lo3, hi3;
        UNPACKD(lo0, hi0, acc[i * 4 + 0]);
        UNPACKD(lo1, hi1, acc[i * 4 + 1]);
        UNPACKD(lo2, hi2, acc[i * 4 + 2]);
        UNPACKD(lo3, hi3, acc[i * 4 + 3]);
        float4 v0 = {lo0, hi0, lo1, hi1};
        float4 v1 = {lo2, hi2, lo3, hi3};
        *(float4*)(o + 0) = v0;
        *(float4*)(o + 4) = v1;
    }
}

// ================= SpMM: y[r,:] = sum_e val*x[col,:] + bias; + BN partials =
// Staged edge words (coalesced once per block), 4 gathers in flight,
// pre-scaled byte offsets.
__global__ void k_spmm(const float* __restrict__ x, const float* __restrict__ bias,
                       float* __restrict__ y) {
    int r = blockIdx.x;
    int t = threadIdx.x;                 // 128 threads, 4 features each
    __shared__ unsigned long long ecv[128];
    __shared__ float4 ssum[128];
    __shared__ float4 ssq[128];
    int s = g_rowstart[r], e = g_rowstart[r + 1];
    const char* xb = (const char*)x + (size_t)t * 16;   // per-thread byte base
    float4 a0 = {0,0,0,0}, a1 = {0,0,0,0}, a2 = {0,0,0,0}, a3 = {0,0,0,0};
    for (int base = s; base < e; base += 128) {
        int n = min(128, e - base);
        __syncthreads();
        if (t < n) ecv[t] = g_ecv[base + t];
        __syncthreads();
        int i = 0;
        for (; i + 4 <= n; i += 4) {
            unsigned long long u0 = ecv[i], u1 = ecv[i+1], u2 = ecv[i+2], u3 = ecv[i+3];
            float v0 = __uint_as_float((unsigned)(u0 >> 32));
            float v1 = __uint_as_float((unsigned)(u1 >> 32));
            float v2 = __uint_as_float((unsigned)(u2 >> 32));
            float v3 = __uint_as_float((unsigned)(u3 >> 32));
            float4 x0 = *(const float4*)(xb + (unsigned)u0);
            float4 x1 = *(const float4*)(xb + (unsigned)u1);
            float4 x2 = *(const float4*)(xb + (unsigned)u2);
            float4 x3 = *(const float4*)(xb + (unsigned)u3);
            a0.x += v0 * x0.x; a0.y += v0 * x0.y; a0.z += v0 * x0.z; a0.w += v0 * x0.w;
            a1.x += v1 * x1.x; a1.y += v1 * x1.y; a1.z += v1 * x1.z; a1.w += v1 * x1.w;
            a2.x += v2 * x2.x; a2.y += v2 * x2.y; a2.z += v2 * x2.z; a2.w += v2 * x2.w;
            a3.x += v3 * x3.x; a3.y += v3 * x3.y; a3.z += v3 * x3.z; a3.w += v3 * x3.w;
        }
        for (; i < n; i++) {
            unsigned long long u = ecv[i];
            float v = __uint_as_float((unsigned)(u >> 32));
            float4 xv = *(const float4*)(xb + (unsigned)u);
            a0.x += v * xv.x; a0.y += v * xv.y; a0.z += v * xv.z; a0.w += v * xv.w;
        }
    }
    float4 acc;
    acc.x = (a0.x + a1.x) + (a2.x + a3.x);
    acc.y = (a0.y + a1.y) + (a2.y + a3.y);
    acc.z = (a0.z + a1.z) + (a2.z + a3.z);
    acc.w = (a0.w + a1.w) + (a2.w + a3.w);
    int c0 = (t & 7) * 4;                // channel base (feature = b*32+c)
    float4 bv = *(const float4*)(bias + c0);
    acc.x += bv.x; acc.y += bv.y; acc.z += bv.z; acc.w += bv.w;
    *(float4*)(y + (size_t)r * FW + t * 4) = acc;
    ssum[t] = acc;
    float4 sq = {acc.x * acc.x, acc.y * acc.y, acc.z * acc.z, acc.w * acc.w};
    ssq[t] = sq;
    __syncthreads();
    if (t < 8) {                         // deterministic reduce over 16 b
        float4 a = {0, 0, 0, 0}, q = {0, 0, 0, 0};
        for (int k = 0; k < 16; k++) {
            float4 u = ssum[k * 8 + t], v = ssq[k * 8 + t];
            a.x += u.x; a.y += u.y; a.z += u.z; a.w += u.w;
            q.x += v.x; q.y += v.y; q.z += v.z; q.w += v.w;
        }
        *(float4*)(g_stats + (size_t)r * 64 + t * 4) = a;
        *(float4*)(g_stats + (size_t)r * 64 + 32 + t * 4) = q;
    }
}

// ================= fused BN reduction (ticket / last-block) ===============
__global__ void k_bn(const float* __restrict__ g, const float* __restrict__ be) {
    int bx = blockIdx.x, t = threadIdx.x;      // grid 64, 256 threads
    int col = t & 63, seg = t >> 6;            // 4 segments x 32 rows
    float s = 0.f;
    int r0 = bx * 128 + seg * 32;
    for (int i = 0; i < 32; i++) s += g_stats[(size_t)(r0 + i) * 64 + col];
    __shared__ float sm[256];
    sm[t] = s;
    __syncthreads();
    if (seg == 0)
        g_stats2[bx * 64 + col] = sm[col] + sm[64 + col] + sm[128 + col] + sm[192 + col];
    __threadfence();
    __shared__ int lastFlag;
    if (t == 0) lastFlag = (atomicAdd(&g_bnticket, 1) == 63);
    __syncthreads();
    if (lastFlag) {
        if (t < 64) {
            float ss = 0.f;
            for (int i = 0; i < 64; i++) ss += g_stats2[i * 64 + t];
            sm[t] = ss;
        }
        __syncthreads();
        if (t < 32) {
            const float inv_n = 1.f / (float)(BSZ * MM);
            float mean = sm[t] * inv_n;
            float var = sm[32 + t] * inv_n - mean * mean;
            float sc = g[t] * rsqrtf(var + 1e-5f);
            g_bn[t] = sc;
            g_bn[32 + t] = be[t] - mean * sc;
        }
        if (t == 0) g_bnticket = 0;   // reset for next use / replay
    }
}

// ================= layer-2 linear, staged + f32x2, fused BN+ReLU ==========
#define L2S 36
__global__ void __launch_bounds__(256) k_lin2(const float* __restrict__ y,
                                              const float* __restrict__ W,
                                              float* __restrict__ out) {
    __shared__ __align__(16) float w[HID * HID];   // 4 KB
    __shared__ __align__(16) float xs[256 * L2S];  // 36 KB
    __shared__ __align__(16) float sc[32], sh[32];
    int t = threadIdx.x;
    {
        const float4* Wv = (const float4*)W;
        float4* wv = (float4*)w;
        if (t < 256) wv[t] = Wv[t];
    }
    if (t < 32) { sc[t] = g_bn[t]; sh[t] = g_bn[32 + t]; }
    __syncthreads();
    int r0 = blockIdx.x * 256;
#pragma unroll
    for (int p = 0; p < 8; p++) {          // stage 2048 float4 with BN+ReLU
        int idx = t + p * 256;
        int r = idx >> 3, f4 = idx & 7;
        float4 v = *(const float4*)(y + ((size_t)(r0 + r)) * HID + f4 * 4);
        float4 s4 = *(const float4*)(sc + f4 * 4);
        float4 h4 = *(const float4*)(sh + f4 * 4);
        float4 o;
        o.x = fmaxf(s4.x * v.x + h4.x, 0.f);
        o.y = fmaxf(s4.y * v.y + h4.y, 0.f);
        o.z = fmaxf(s4.z * v.z + h4.z, 0.f);
        o.w = fmaxf(s4.w * v.w + h4.w, 0.f);
        *(float4*)(xs + r * L2S + f4 * 4) = o;
    }
    __syncthreads();
    int rp = t >> 1;
    int h = t & 1;
    const float* xr0 = xs + (2 * rp) * L2S;
    const float* xr1 = xr0 + L2S;
    unsigned long long acc0[8], acc1[8];
#pragma unroll
    for (int i = 0; i < 8; i++) { acc0[i] = 0ULL; acc1[i] = 0ULL; }
#pragma unroll
    for (int k4 = 0; k4 < HID / 4; k4++) {
        float4 xa = *(const float4*)(xr0 + k4 * 4);
        float4 xb = *(const float4*)(xr1 + k4 * 4);
#pragma unroll
        for (int kk = 0; kk < 4; kk++) {
            float e0 = (kk == 0) ? xa.x : (kk == 1) ? xa.y : (kk == 2) ? xa.z : xa.w;
            float e1 = (kk == 0) ? xb.x : (kk == 1) ? xb.y : (kk == 2) ? xb.z : xb.w;
            unsigned long long d0, d1;
            PACKD(d0, e0, e0); PACKD(d1, e1, e1);
            const ulonglong2* wr = (const ulonglong2*)(w + (k4 * 4 + kk) * HID + h * 16);
#pragma unroll
            for (int q = 0; q < 4; q++) {
                ulonglong2 wp = wr[q];
                FMA2(acc0[2 * q + 0], d0, wp.x, acc0[2 * q + 0]);
                FMA2(acc0[2 * q + 1], d0, wp.y, acc0[2 * q + 1]);
                FMA2(acc1[2 * q + 0], d1, wp.x, acc1[2 * q + 0]);
                FMA2(acc1[2 * q + 1], d1, wp.y, acc1[2 * q + 1]);
            }
        }
    }
    float* o0 = out + ((size_t)(r0 + 2 * rp)) * HID + h * 16;
    float* o1 = o0 + HID;
#pragma unroll
    for (int q = 0; q < 4; q++) {
        float lo0, hi0, lo1, hi1;
        UNPACKD(lo0, hi0, acc0[2 * q + 0]);
        UNPACKD(lo1, hi1, acc0[2 * q + 1]);
        float4 v = {lo0, hi0, lo1, hi1};
        *(float4*)(o0 + q * 4) = v;
    }
#pragma unroll
    for (int q = 0; q < 4; q++) {
        float lo0, hi0, lo1, hi1;
        UNPACKD(lo0, hi0, acc1[2 * q + 0]);
        UNPACKD(lo1, hi1, acc1[2 * q + 1]);
        float4 v = {lo0, hi0, lo1, hi1};
        *(float4*)(o1 + q * 4) = v;
    }
}

// ================= fc1 split-K GEMM: LDG.128, depth-4 prefetch, f32x2 =====
// Measured-best config: NKCH=512, MPC=16, 128 thr, thread owns a j-quad;
// x reads are same-address smem broadcasts (stride 16, 32.8 KB).
#define FC1_STEP(F, KCC) do {                                               \
    unsigned long long w2[4];                                               \
    PACKD(w2[0], (F).x, (F).x); PACKD(w2[1], (F).y, (F).y);                 \
    PACKD(w2[2], (F).z, (F).z); PACKD(w2[3], (F).w, (F).w);                 \
    const ulonglong2* xp = (const ulonglong2*)(xs + (KCC) * 16);            \
    ulonglong2 xA = xp[0], xB = xp[1], xC = xp[2], xD = xp[3];              \
    unsigned long long xv[8] = {xA.x, xA.y, xB.x, xB.y,                     \
                                xC.x, xC.y, xD.x, xD.y};                    \
    _Pragma("unroll")                                                       \
    for (int j = 0; j < 4; j++) {                                           \
        _Pragma("unroll")                                                   \
        for (int bp = 0; bp < 8; bp++)                                      \
            FMA2(acc[j * 8 + bp], xv[bp], w2[j], acc[j * 8 + bp]);          \
    }                                                                       \
} while (0)

__global__ void __launch_bounds__(128) k_fc1(const float* __restrict__ w,
                                             const float* __restrict__ y2) {
    int ck = blockIdx.x;                  // K-chunk: m in [ck*16, ck*16+16)
    int t = threadIdx.x;                  // 128
    __shared__ __align__(16) float xs[MPC * HID * 16];  // 32.8 KB, stride 16
    __shared__ float sc[32], sh[32];
    if (t < 32) { sc[t] = g_bn[t]; sh[t] = g_bn[32 + t]; }
    __syncthreads();
    {   // stage 16 rows: BN + ReLU + transpose to xs[kc*16 + b]
        int c0 = (t & 7) * 4;
        int b = t >> 3;
        float s0 = sc[c0 + 0], s1 = sc[c0 + 1], s2 = sc[c0 + 2], s3 = sc[c0 + 3];
        float h0 = sh[c0 + 0], h1 = sh[c0 + 1], h2 = sh[c0 + 2], h3 = sh[c0 + 3];
#pragma unroll
        for (int mi = 0; mi < MPC; mi++) {
            float4 v = *(const float4*)(y2 + ((size_t)(ck * MPC + mi)) * FW + t * 4);
            float* xr = xs + (mi * HID + c0) * 16;
            xr[b]      = fmaxf(s0 * v.x + h0, 0.f);
            xr[16 + b] = fmaxf(s1 * v.y + h1, 0.f);
            xr[32 + b] = fmaxf(s2 * v.z + h2, 0.f);
            xr[48 + b] = fmaxf(s3 * v.w + h3, 0.f);
        }
    }
    __syncthreads();
    unsigned long long acc[32];           // acc[j(4)][b-pair(8)]
#pragma unroll
    for (int i = 0; i < 32; i++) acc[i] = 0ULL;
    int j0 = t * 4;
    const float* wp = w + (size_t)ck * (MPC * HID) * FW + j0;
    // depth-4 rolling prefetch; reads up to 3 rows past the chunk, safe since
    // w has KTOT+32 rows and the last chunk ends 31 rows before the end.
    float4 f0 = *(const float4*)(wp + 0 * FW);
    float4 f1 = *(const float4*)(wp + 1 * FW);
    float4 f2 = *(const float4*)(wp + 2 * FW);
    float4 f3 = *(const float4*)(wp + 3 * FW);
#pragma unroll 1
    for (int kc = 0; kc < MPC * HID - 4; kc += 4) {
        float4 n0 = *(const float4*)(wp + (size_t)(kc + 4) * FW);
        float4 n1 = *(const float4*)(wp + (size_t)(kc + 5) * FW);
        float4 n2 = *(const float4*)(wp + (size_t)(kc + 6) * FW);
        float4 n3 = *(const float4*)(wp + (size_t)(kc + 7) * FW);
        FC1_STEP(f0, kc + 0);
        FC1_STEP(f1, kc + 1);
        FC1_STEP(f2, kc + 2);
        FC1_STEP(f3, kc + 3);
        f0 = n0; f1 = n1; f2 = n2; f3 = n3;
    }
    FC1_STEP(f0, MPC * HID - 4);
    FC1_STEP(f1, MPC * HID - 3);
    FC1_STEP(f2, MPC * HID - 2);
    FC1_STEP(f3, MPC * HID - 1);
    float* pbase = g_part + (size_t)ck * BSZ * FW + j0;
#pragma unroll
    for (int bp = 0; bp < 8; bp++) {      // b-pair bp -> rows 2bp, 2bp+1
        float lo0, hi0, lo1, hi1, lo2, hi2, lo3, hi3;
        UNPACKD(lo0, hi0, acc[0 * 8 + bp]);
        UNPACKD(lo1, hi1, acc[1 * 8 + bp]);
        UNPACKD(lo2, hi2, acc[2 * 8 + bp]);
        UNPACKD(lo3, hi3, acc[3 * 8 + bp]);
        float4 e = {lo0, lo1, lo2, lo3};
        float4 o = {hi0, hi1, hi2, hi3};
        *(float4*)(pbase + (size_t)(2 * bp + 0) * FW) = e;
        *(float4*)(pbase + (size_t)(2 * bp + 1) * FW) = o;
    }
}

// ================= reduce partials (stage 1, coalesced float4) ============
__global__ void k_red1() {
    int b = blockIdx.x >> 3;             // 0..15
    int grp = blockIdx.x & 7;            // 0..7, each covers 64 chunks
    int t = threadIdx.x;                 // 128 threads, j-quad each
    const float* p = g_part + (size_t)(grp * 64) * BSZ * FW + (size_t)b * FW + t * 4;
    float4 s = {0, 0, 0, 0};
#pragma unroll 8
    for (int k = 0; k < 64; k++) {
        float4 v = *(const float4*)(p + (size_t)k * BSZ * FW);
        s.x += v.x; s.y += v.y; s.z += v.z; s.w += v.w;
    }
    *(float4*)(g_red + (size_t)(b * 8 + grp) * FW + t * 4) = s;
}

// ================= final: reduce + extras + bias + relu + fc2 =============
__global__ void k_red2(const float* __restrict__ w, const float* __restrict__ fc1b,
                       const float* __restrict__ ex, const float* __restrict__ fc2w,
                       const float* __restrict__ fc2b, float* __restrict__ out) {
    int b = blockIdx.x;                  // 16 blocks
    int j = threadIdx.x;                 // 512 threads
    float acc = fc1b[j];
#pragma unroll
    for (int g = 0; g < 8; g++) acc += g_red[(size_t)(b * 8 + g) * FW + j];
#pragma unroll
    for (int e2 = 0; e2 < 32; e2++)
        acc += ex[b * 32 + e2] * w[((size_t)KTOT + e2) * FW + j];
    float h = fmaxf(acc, 0.f);
    __shared__ float r0[512], r1[512];
    r0[j] = h * fc2w[j * 2 + 0];
    r1[j] = h * fc2w[j * 2 + 1];
    __syncthreads();
    for (int s = 256; s > 0; s >>= 1) {
        if (j < s) { r0[j] += r0[j + s]; r1[j] += r1[j + s]; }
        __syncthreads();
    }
    if (j == 0) {
        out[b * 2 + 0] = r0[0] + fc2b[0];
        out[b * 2 + 1] = r1[0] + fc2b[1];
    }
}

// ================= launch ==================================================
extern "C" void kernel_launch(void* const* d_in, const int* in_sizes, int n_in,
                              void* d_out, int out_size) {
    const float* inputs  = (const float*)d_in[0];
    const float* ex      = (const float*)d_in[1];
    const int*   erow    = (const int*)  d_in[2];
    const int*   ecol    = (const int*)  d_in[3];
    const float* eval    = (const float*)d_in[4];
    const float* W1      = (const float*)d_in[5];
    const float* b1      = (const float*)d_in[6];
    const float* g1      = (const float*)d_in[7];
    const float* be1     = (const float*)d_in[8];
    const float* W2      = (const float*)d_in[9];
    const float* b2      = (const float*)d_in[10];
    const float* g2      = (const float*)d_in[11];
    const float* be2     = (const float*)d_in[12];
    const float* fc1w    = (const float*)d_in[13];
    const float* fc1b    = (const float*)d_in[14];
    const float* fc2w    = (const float*)d_in[15];
    const float* fc2b    = (const float*)d_in[16];
    float* out = (float*)d_out;

    float* bufA; cudaGetSymbolAddress((void**)&bufA, g_bufA);
    float* bufB; cudaGetSymbolAddress((void**)&bufB, g_bufB);
    int* cnt;    cudaGetSymbolAddress((void**)&cnt,  g_count);

    // Kernel order: spmm is the 4th kernel launch -> profiled by ncu.
    cudaMemsetAsync(cnt, 0, MM * sizeof(int));
    k_histscan<<<NNZ / 1024, 256>>>(erow);                  // k1: hist+scan fused
    k_lin1<<<MM / 16, 256>>>(inputs, W1);                   // k2: bufA = X@W1
    k_scatter<<<NNZ / 1024, 256>>>(erow, ecol, eval);       // k3
    k_spmm<<<MM, 128>>>(bufA, b1, bufB);                    // k4 (profiled)
    k_bn<<<64, 256>>>(g1, be1);
    k_lin2<<<(BSZ * MM) / 256, 256>>>(bufB, W2, bufA);      // bufA = bnrelu(bufB)@W2
    k_spmm<<<MM, 128>>>(bufA, b2, bufB);                    // bufB = L@bufA + b2
    k_bn<<<64, 256>>>(g2, be2);

    k_fc1<<<NKCH, 128>>>(fc1w, bufB);                       // split-K partials
    k_red1<<<BSZ * 8, 128>>>();                             // coalesced partial reduce
    k_red2<<<BSZ, 512>>>(fc1w, fc1b, ex, fc2w, fc2b, out);  // finish + fc2
}

// round 14
// speedup vs baseline: 1.3736x; 1.0285x over previous
#include <cuda_runtime.h>
#include <cuda_bf16.h>

#define MM    8192
#define BSZ   16
#define HID   32
#define WIN   64
#define NNZ   131072
#define FW    512          // BSZ*HID features per node-row
#define NKCH  512          // fc1 split-K chunks
#define MPC   16           // m-rows per fc1 chunk (MM/NKCH)
#define KTOT  262144       // MM*HID
#define NST   4            // fc1 TMA pipeline stages
#define SROWS 8            // w rows per stage (16 KB)
#define NCHUNK (MPC * HID / SROWS)   // 64

// ---------------- scratch (static device globals; no runtime alloc) -------
__device__ int   g_count[MM];
__device__ int   g_rowstart[MM + 1];
__device__ int   g_cursor[MM];
__device__ int   g_csrticket;
__device__ unsigned long long g_ecv[NNZ];   // packed (val<<32 | col*FW*4)
__device__ float g_bufA[MM * FW];           // 16 MB
__device__ float g_bufB[MM * FW];           // 16 MB
__device__ float g_stats[MM * 64];          // per-row [sum(32), sumsq(32)]
__device__ float g_stats2[64 * 64];
__device__ float g_bn[64];                  // scale[32], shift[32]
__device__ int   g_bnticket;
__device__ float g_part[NKCH * BSZ * FW];   // 16 MB fc1 split-K partials
__device__ float g_red[BSZ * 8 * FW];       // stage-1 reduced partials

// ---------------- f32x2 packed-FMA helpers (sm_103a) ----------------------
#define FMA2(d, a, b, c) asm("fma.rn.f32x2 %0, %1, %2, %3;" \
    : "=l"(d) : "l"(a), "l"(b), "l"(c))
#define PACKD(d, lo, hi) asm("mov.b64 %0, {%1, %2};" \
    : "=l"(d) : "f"(lo), "f"(hi))
#define UNPACKD(lo, hi, d) asm("mov.b64 {%0, %1}, %2;" \
    : "=f"(lo), "=f"(hi) : "l"(d))

// ---------------- TMA / mbarrier helpers ----------------------------------
__device__ __forceinline__ unsigned smem_u32(const void* p) {
    unsigned a;
    asm("{ .reg .u64 tmp; cvta.to.shared.u64 tmp, %1; cvt.u32.u64 %0, tmp; }"
        : "=r"(a) : "l"(p));
    return a;
}
#define MBARRIER_INIT(mb, cnt) \
    asm volatile("mbarrier.init.shared.b64 [%0], %1;" \
        :: "r"((unsigned)(mb)), "r"((unsigned)(cnt)) : "memory")
#define MBARRIER_EXPECT_TX(mb, bytes) \
    asm volatile("mbarrier.arrive.expect_tx.shared.b64 _, [%0], %1;" \
        :: "r"((unsigned)(mb)), "r"((unsigned)(bytes)) : "memory")
#define BULK_G2S(dst, src, bytes, mb) \
    asm volatile("cp.async.bulk.shared::cluster.global.mbarrier::complete_tx::bytes [%0], [%1], %2, [%3];" \
        :: "r"((unsigned)(dst)), "l"(src), "r"((unsigned)(bytes)), "r"((unsigned)(mb)) : "memory")
#define MBARRIER_WAIT_PARITY(mb, par) do {                                   \
    unsigned _mb = (unsigned)(mb);                                           \
    unsigned _par = (unsigned)(par);                                         \
    unsigned _done;                                                          \
    asm volatile("{\n\t.reg .pred p;\n\t"                                    \
        "mbarrier.try_wait.parity.shared.b64 p, [%1], %2;\n\t"               \
        "selp.b32 %0, 1, 0, p;\n\t}"                                         \
        : "=r"(_done) : "r"(_mb), "r"(_par) : "memory");                     \
    if (!_done) {                                                            \
        asm volatile("{\n\t.reg .pred P1;\n\t"                               \
            "WAIT_LOOP_%=:\n\t"                                              \
            "mbarrier.try_wait.parity.shared.b64 P1, [%0], %1;\n\t"          \
            "@P1 bra.uni WAIT_DONE_%=;\n\t"                                  \
            "bra.uni WAIT_LOOP_%=;\n\t"                                      \
            "WAIT_DONE_%=:\n\t}"                                             \
            :: "r"(_mb), "r"(_par) : "memory");                              \
    }                                                                        \
} while (0)

// ================= CSR build: fused hist + scan (ticket) ==================
__global__ void k_histscan(const int* __restrict__ row) {
    int e0 = (blockIdx.x * 256 + threadIdx.x) * 4;
    int4 r = *(const int4*)(row + e0);
    atomicAdd(&g_count[r.x], 1);
    atomicAdd(&g_count[r.y], 1);
    atomicAdd(&g_count[r.z], 1);
    atomicAdd(&g_count[r.w], 1);
    __threadfence();
    __shared__ int lastFlag;
    if (threadIdx.x == 0)
        lastFlag = (atomicAdd(&g_csrticket, 1) == (int)gridDim.x - 1);
    __syncthreads();
    if (!lastFlag) return;
    int t = threadIdx.x;
    int loc[32];
    int s = 0;
#pragma unroll
    for (int i = 0; i < 32; i++) { loc[i] = g_count[t * 32 + i]; s += loc[i]; }
    __shared__ int sm[256];
    sm[t] = s;
    __syncthreads();
    for (int off = 1; off < 256; off <<= 1) {
        int v = (t >= off) ? sm[t - off] : 0;
        __syncthreads();
        sm[t] += v;
        __syncthreads();
    }
    int run = (t == 0) ? 0 : sm[t - 1];
#pragma unroll
    for (int i = 0; i < 32; i++) {
        g_rowstart[t * 32 + i] = run;
        g_cursor[t * 32 + i] = run;
        run += loc[i];
    }
    if (t == 255) g_rowstart[MM] = run;
    if (t == 0) g_csrticket = 0;       // reset for replay
}

__global__ void k_scatter(const int* __restrict__ row, const int* __restrict__ col,
                          const float* __restrict__ val) {
    int e0 = (blockIdx.x * 256 + threadIdx.x) * 4;
    int4 r = *(const int4*)(row + e0);
    int4 c = *(const int4*)(col + e0);
    float4 v = *(const float4*)(val + e0);
    // low word = col * FW * 4 (byte offset into x), so spmm does 1 add
    int p0 = atomicAdd(&g_cursor[r.x], 1);
    g_ecv[p0] = ((unsigned long long)__float_as_uint(v.x) << 32) | ((unsigned)c.x * (FW * 4u));
    int p1 = atomicAdd(&g_cursor[r.y], 1);
    g_ecv[p1] = ((unsigned long long)__float_as_uint(v.y) << 32) | ((unsigned)c.y * (FW * 4u));
    int p2 = atomicAdd(&g_cursor[r.z], 1);
    g_ecv[p2] = ((unsigned long long)__float_as_uint(v.z) << 32) | ((unsigned)c.z * (FW * 4u));
    int p3 = atomicAdd(&g_cursor[r.w], 1);
    g_ecv[p3] = ((unsigned long long)__float_as_uint(v.w) << 32) | ((unsigned)c.w * (FW * 4u));
}

// ================= layer-1 linear: bufA[(m,b),:] = inputs[b,m,:] @ W1 =====
#define L1S 68
__global__ void __launch_bounds__(256) k_lin1(const float* __restrict__ x,
                                              const float* __restrict__ W) {
    __shared__ __align__(16) float w[WIN * HID];   // 8 KB
    __shared__ __align__(16) float xs[256 * L1S];  // 68 KB
    int t = threadIdx.x;
    int m0 = blockIdx.x * 16;
    {
        const float4* Wv = (const float4*)W;
        float4* wv = (float4*)w;
#pragma unroll
        for (int p = 0; p < 2; p++) wv[t + p * 256] = Wv[t + p * 256];
    }
#pragma unroll
    for (int p = 0; p < 16; p++) {        // stage 4096 float4
        int idx = t + p * 256;
        int r = idx >> 4, f4 = idx & 15;  // r = mm*16 + b
        int b = r & 15, mm = r >> 4;
        float4 v = *(const float4*)(x + ((size_t)b * MM + m0 + mm) * WIN + f4 * 4);
        *(float4*)(xs + r * L1S + f4 * 4) = v;
    }
    __syncthreads();
    int rg = t >> 2;                      // rows 4rg .. 4rg+3
    int cg = t & 3;                       // channels cg*8 .. cg*8+7 (4 pairs)
    const float* xr = xs + (4 * rg) * L1S;
    unsigned long long acc[16];           // acc[row i][pair p] = acc[i*4+p]
#pragma unroll
    for (int i = 0; i < 16; i++) acc[i] = 0ULL;
#pragma unroll 4
    for (int k4 = 0; k4 < WIN / 4; k4++) {
        float4 xv0 = *(const float4*)(xr + 0 * L1S + k4 * 4);
        float4 xv1 = *(const float4*)(xr + 1 * L1S + k4 * 4);
        float4 xv2 = *(const float4*)(xr + 2 * L1S + k4 * 4);
        float4 xv3 = *(const float4*)(xr + 3 * L1S + k4 * 4);
#pragma unroll
        for (int kk = 0; kk < 4; kk++) {
            float e0 = (kk == 0) ? xv0.x : (kk == 1) ? xv0.y : (kk == 2) ? xv0.z : xv0.w;
            float e1 = (kk == 0) ? xv1.x : (kk == 1) ? xv1.y : (kk == 2) ? xv1.z : xv1.w;
            float e2 = (kk == 0) ? xv2.x : (kk == 1) ? xv2.y : (kk == 2) ? xv2.z : xv2.w;
            float e3 = (kk == 0) ? xv3.x : (kk == 1) ? xv3.y : (kk == 2) ? xv3.z : xv3.w;
            unsigned long long d0, d1, d2, d3;
            PACKD(d0, e0, e0); PACKD(d1, e1, e1);
            PACKD(d2, e2, e2); PACKD(d3, e3, e3);
            const ulonglong2* wr =
                (const ulonglong2*)(w + (k4 * 4 + kk) * HID + cg * 8);
            ulonglong2 wa = wr[0];
            ulonglong2 wb = wr[1];
            FMA2(acc[0 * 4 + 0], d0, wa.x, acc[0 * 4 + 0]);
            FMA2(acc[0 * 4 + 1], d0, wa.y, acc[0 * 4 + 1]);
            FMA2(acc[0 * 4 + 2], d0, wb.x, acc[0 * 4 + 2]);
            FMA2(acc[0 * 4 + 3], d0, wb.y, acc[0 * 4 + 3]);
            FMA2(acc[1 * 4 + 0], d1, wa.x, acc[1 * 4 + 0]);
            FMA2(acc[1 * 4 + 1], d1, wa.y, acc[1 * 4 + 1]);
            FMA2(acc[1 * 4 + 2], d1, wb.x, acc[1 * 4 + 2]);
            FMA2(acc[1 * 4 + 3], d1, wb.y, acc[1 * 4 + 3]);
            FMA2(acc[2 * 4 + 0], d2, wa.x, acc[2 * 4 + 0]);
            FMA2(acc[2 * 4 + 1], d2, wa.y, acc[2 * 4 + 1]);
            FMA2(acc[2 * 4 + 2], d2, wb.x, acc[2 * 4 + 2]);
            FMA2(acc[2 * 4 + 3], d2, wb.y, acc[2 * 4 + 3]);
            FMA2(acc[3 * 4 + 0], d3, wa.x, acc[3 * 4 + 0]);
            FMA2(acc[3 * 4 + 1], d3, wa.y, acc[3 * 4 + 1]);
            FMA2(acc[3 * 4 + 2], d3, wb.x, acc[3 * 4 + 2]);
            FMA2(acc[3 * 4 + 3], d3, wb.y, acc[3 * 4 + 3]);
        }
    }
#pragma unroll
    for (int i = 0; i < 4; i++) {
        int r = 4 * rg + i;
        int b = r & 15, mm = r >> 4;
        float* o = g_bufA + (((size_t)(m0 + mm) * BSZ) + b) * HID + cg * 8;
        float lo0, hi0, lo1, hi1, lo2, hi2, lo3, hi3;
        UNPACKD(lo0, hi0, acc[i * 4 + 0]);
        UNPACKD(lo1, hi1, acc[i * 4 + 1]);
        UNPACKD(lo2, hi2, acc[i * 4 + 2]);
        UNPACKD(lo3, hi3, acc[i * 4 + 3]);
        float4 v0 = {lo0, hi0, lo1, hi1};
        float4 v1 = {lo2, hi2, lo3, hi3};
        *(float4*)(o + 0) = v0;
        *(float4*)(o + 4) = v1;
    }
}

// ================= SpMM: y[r,:] = sum_e val*x[col,:] + bias; + BN partials =
__global__ void k_spmm(const float* __restrict__ x, const float* __restrict__ bias,
                       float* __restrict__ y) {
    int r = blockIdx.x;
    int t = threadIdx.x;                 // 128 threads, 4 features each
    __shared__ unsigned long long ecv[128];
    __shared__ float4 ssum[128];
    __shared__ float4 ssq[128];
    int s = g_rowstart[r], e = g_rowstart[r + 1];
    const char* xb = (const char*)x + (size_t)t * 16;   // per-thread byte base
    float4 a0 = {0,0,0,0}, a1 = {0,0,0,0}, a2 = {0,0,0,0}, a3 = {0,0,0,0};
    for (int base = s; base < e; base += 128) {
        int n = min(128, e - base);
        __syncthreads();
        if (t < n) ecv[t] = g_ecv[base + t];
        __syncthreads();
        int i = 0;
        for (; i + 4 <= n; i += 4) {
            unsigned long long u0 = ecv[i], u1 = ecv[i+1], u2 = ecv[i+2], u3 = ecv[i+3];
            float v0 = __uint_as_float((unsigned)(u0 >> 32));
            float v1 = __uint_as_float((unsigned)(u1 >> 32));
            float v2 = __uint_as_float((unsigned)(u2 >> 32));
            float v3 = __uint_as_float((unsigned)(u3 >> 32));
            float4 x0 = *(const float4*)(xb + (unsigned)u0);
            float4 x1 = *(const float4*)(xb + (unsigned)u1);
            float4 x2 = *(const float4*)(xb + (unsigned)u2);
            float4 x3 = *(const float4*)(xb + (unsigned)u3);
            a0.x += v0 * x0.x; a0.y += v0 * x0.y; a0.z += v0 * x0.z; a0.w += v0 * x0.w;
            a1.x += v1 * x1.x; a1.y += v1 * x1.y; a1.z += v1 * x1.z; a1.w += v1 * x1.w;
            a2.x += v2 * x2.x; a2.y += v2 * x2.y; a2.z += v2 * x2.z; a2.w += v2 * x2.w;
            a3.x += v3 * x3.x; a3.y += v3 * x3.y; a3.z += v3 * x3.z; a3.w += v3 * x3.w;
        }
        for (; i < n; i++) {
            unsigned long long u = ecv[i];
            float v = __uint_as_float((unsigned)(u >> 32));
            float4 xv = *(const float4*)(xb + (unsigned)u);
            a0.x += v * xv.x; a0.y += v * xv.y; a0.z += v * xv.z; a0.w += v * xv.w;
        }
    }
    float4 acc;
    acc.x = (a0.x + a1.x) + (a2.x + a3.x);
    acc.y = (a0.y + a1.y) + (a2.y + a3.y);
    acc.z = (a0.z + a1.z) + (a2.z + a3.z);
    acc.w = (a0.w + a1.w) + (a2.w + a3.w);
    int c0 = (t & 7) * 4;                // channel base (feature = b*32+c)
    float4 bv = *(const float4*)(bias + c0);
    acc.x += bv.x; acc.y += bv.y; acc.z += bv.z; acc.w += bv.w;
    *(float4*)(y + (size_t)r * FW + t * 4) = acc;
    ssum[t] = acc;
    float4 sq = {acc.x * acc.x, acc.y * acc.y, acc.z * acc.z, acc.w * acc.w};
    ssq[t] = sq;
    __syncthreads();
    if (t < 8) {                         // deterministic reduce over 16 b
        float4 a = {0, 0, 0, 0}, q = {0, 0, 0, 0};
        for (int k = 0; k < 16; k++) {
            float4 u = ssum[k * 8 + t], v = ssq[k * 8 + t];
            a.x += u.x; a.y += u.y; a.z += u.z; a.w += u.w;
            q.x += v.x; q.y += v.y; q.z += v.z; q.w += v.w;
        }
        *(float4*)(g_stats + (size_t)r * 64 + t * 4) = a;
        *(float4*)(g_stats + (size_t)r * 64 + 32 + t * 4) = q;
    }
}

// ================= fused BN reduction (ticket / last-block) ===============
__global__ void k_bn(const float* __restrict__ g, const float* __restrict__ be) {
    int bx = blockIdx.x, t = threadIdx.x;      // grid 64, 256 threads
    int col = t & 63, seg = t >> 6;            // 4 segments x 32 rows
    float s = 0.f;
    int r0 = bx * 128 + seg * 32;
    for (int i = 0; i < 32; i++) s += g_stats[(size_t)(r0 + i) * 64 + col];
    __shared__ float sm[256];
    sm[t] = s;
    __syncthreads();
    if (seg == 0)
        g_stats2[bx * 64 + col] = sm[col] + sm[64 + col] + sm[128 + col] + sm[192 + col];
    __threadfence();
    __shared__ int lastFlag;
    if (t == 0) lastFlag = (atomicAdd(&g_bnticket, 1) == 63);
    __syncthreads();
    if (lastFlag) {
        if (t < 64) {
            float ss = 0.f;
            for (int i = 0; i < 64; i++) ss += g_stats2[i * 64 + t];
            sm[t] = ss;
        }
        __syncthreads();
        if (t < 32) {
            const float inv_n = 1.f / (float)(BSZ * MM);
            float mean = sm[t] * inv_n;
            float var = sm[32 + t] * inv_n - mean * mean;
            float sc = g[t] * rsqrtf(var + 1e-5f);
            g_bn[t] = sc;
            g_bn[32 + t] = be[t] - mean * sc;
        }
        if (t == 0) g_bnticket = 0;   // reset for next use / replay
    }
}

// ================= layer-2 linear, staged + f32x2, fused BN+ReLU ==========
#define L2S 36
__global__ void __launch_bounds__(256) k_lin2(const float* __restrict__ y,
                                              const float* __restrict__ W,
                                              float* __restrict__ out) {
    __shared__ __align__(16) float w[HID * HID];   // 4 KB
    __shared__ __align__(16) float xs[256 * L2S];  // 36 KB
    __shared__ __align__(16) float sc[32], sh[32];
    int t = threadIdx.x;
    {
        const float4* Wv = (const float4*)W;
        float4* wv = (float4*)w;
        if (t < 256) wv[t] = Wv[t];
    }
    if (t < 32) { sc[t] = g_bn[t]; sh[t] = g_bn[32 + t]; }
    __syncthreads();
    int r0 = blockIdx.x * 256;
#pragma unroll
    for (int p = 0; p < 8; p++) {          // stage 2048 float4 with BN+ReLU
        int idx = t + p * 256;
        int r = idx >> 3, f4 = idx & 7;
        float4 v = *(const float4*)(y + ((size_t)(r0 + r)) * HID + f4 * 4);
        float4 s4 = *(const float4*)(sc + f4 * 4);
        float4 h4 = *(const float4*)(sh + f4 * 4);
        float4 o;
        o.x = fmaxf(s4.x * v.x + h4.x, 0.f);
        o.y = fmaxf(s4.y * v.y + h4.y, 0.f);
        o.z = fmaxf(s4.z * v.z + h4.z, 0.f);
        o.w = fmaxf(s4.w * v.w + h4.w, 0.f);
        *(float4*)(xs + r * L2S + f4 * 4) = o;
    }
    __syncthreads();
    int rp = t >> 1;
    int h = t & 1;
    const float* xr0 = xs + (2 * rp) * L2S;
    const float* xr1 = xr0 + L2S;
    unsigned long long acc0[8], acc1[8];
#pragma unroll
    for (int i = 0; i < 8; i++) { acc0[i] = 0ULL; acc1[i] = 0ULL; }
#pragma unroll
    for (int k4 = 0; k4 < HID / 4; k4++) {
        float4 xa = *(const float4*)(xr0 + k4 * 4);
        float4 xb = *(const float4*)(xr1 + k4 * 4);
#pragma unroll
        for (int kk = 0; kk < 4; kk++) {
            float e0 = (kk == 0) ? xa.x : (kk == 1) ? xa.y : (kk == 2) ? xa.z : xa.w;
            float e1 = (kk == 0) ? xb.x : (kk == 1) ? xb.y : (kk == 2) ? xb.z : xb.w;
            unsigned long long d0, d1;
            PACKD(d0, e0, e0); PACKD(d1, e1, e1);
            const ulonglong2* wr = (const ulonglong2*)(w + (k4 * 4 + kk) * HID + h * 16);
#pragma unroll
            for (int q = 0; q < 4; q++) {
                ulonglong2 wp = wr[q];
                FMA2(acc0[2 * q + 0], d0, wp.x, acc0[2 * q + 0]);
                FMA2(acc0[2 * q + 1], d0, wp.y, acc0[2 * q + 1]);
                FMA2(acc1[2 * q + 0], d1, wp.x, acc1[2 * q + 0]);
                FMA2(acc1[2 * q + 1], d1, wp.y, acc1[2 * q + 1]);
            }
        }
    }
    float* o0 = out + ((size_t)(r0 + 2 * rp)) * HID + h * 16;
    float* o1 = o0 + HID;
#pragma unroll
    for (int q = 0; q < 4; q++) {
        float lo0, hi0, lo1, hi1;
        UNPACKD(lo0, hi0, acc0[2 * q + 0]);
        UNPACKD(lo1, hi1, acc0[2 * q + 1]);
        float4 v = {lo0, hi0, lo1, hi1};
        *(float4*)(o0 + q * 4) = v;
    }
#pragma unroll
    for (int q = 0; q < 4; q++) {
        float lo0, hi0, lo1, hi1;
        UNPACKD(lo0, hi0, acc1[2 * q + 0]);
        UNPACKD(lo1, hi1, acc1[2 * q + 1]);
        float4 v = {lo0, hi0, lo1, hi1};
        *(float4*)(o1 + q * 4) = v;
    }
}

// ================= fc1 split-K GEMM: TMA bulk pipeline + f32x2 ============
// Per-block weight slab (rows ck*512..+512 x 512 cols) is contiguous 1 MB.
// 4-stage x 16 KB cp.async.bulk ring; mainloop is pure LDS+FMA2.
#define FC1_STEP(F, KCC) do {                                               \
    unsigned long long w2[4];                                               \
    PACKD(w2[0], (F).x, (F).x); PACKD(w2[1], (F).y, (F).y);                 \
    PACKD(w2[2], (F).z, (F).z); PACKD(w2[3], (F).w, (F).w);                 \
    const ulonglong2* xp = (const ulonglong2*)(xs + (KCC) * 16);            \
    ulonglong2 xA = xp[0], xB = xp[1], xC = xp[2], xD = xp[3];              \
    unsigned long long xv[8] = {xA.x, xA.y, xB.x, xB.y,                     \
                                xC.x, xC.y, xD.x, xD.y};                    \
    _Pragma("unroll")                                                       \
    for (int j = 0; j < 4; j++) {                                           \
        _Pragma("unroll")                                                   \
        for (int bp = 0; bp < 8; bp++)                                      \
            FMA2(acc[j * 8 + bp], xv[bp], w2[j], acc[j * 8 + bp]);          \
    }                                                                       \
} while (0)

__global__ void __launch_bounds__(128) k_fc1(const float* __restrict__ w,
                                             const float* __restrict__ y2) {
    int ck = blockIdx.x;                  // K-chunk: m in [ck*16, ck*16+16)
    int t = threadIdx.x;                  // 128
    __shared__ __align__(16) float xs[MPC * HID * 16];       // 32.8 KB
    __shared__ __align__(16) float ws[NST][SROWS * FW];      // 64 KB ring
    __shared__ __align__(8) unsigned long long mbar[NST];
    __shared__ float sc[32], sh[32];
    if (t < 32) { sc[t] = g_bn[t]; sh[t] = g_bn[32 + t]; }
    unsigned mb0 = smem_u32(&mbar[0]);
    unsigned ws0 = smem_u32(&ws[0][0]);
    if (t == 0) {
#pragma unroll
        for (int s = 0; s < NST; s++) MBARRIER_INIT(mb0 + 8 * s, 1);
    }
    __syncthreads();
    const char* wsrc = (const char*)(w + (size_t)ck * (MPC * HID) * FW);
    const unsigned STB = SROWS * FW * 4;  // 16384 bytes per stage
    if (t == 0) {                         // prefill all NST stages
#pragma unroll
        for (int s = 0; s < NST; s++) {
            MBARRIER_EXPECT_TX(mb0 + 8 * s, STB);
            BULK_G2S(ws0 + s * STB, wsrc + (size_t)s * STB, STB, mb0 + 8 * s);
        }
    }
    {   // stage 16 x-rows: BN + ReLU + transpose to xs[kc*16 + b]
        int c0 = (t & 7) * 4;
        int b = t >> 3;
        float s0 = sc[c0 + 0], s1 = sc[c0 + 1], s2 = sc[c0 + 2], s3 = sc[c0 + 3];
        float h0 = sh[c0 + 0], h1 = sh[c0 + 1], h2 = sh[c0 + 2], h3 = sh[c0 + 3];
#pragma unroll
        for (int mi = 0; mi < MPC; mi++) {
            float4 v = *(const float4*)(y2 + ((size_t)(ck * MPC + mi)) * FW + t * 4);
            float* xr = xs + (mi * HID + c0) * 16;
            xr[b]      = fmaxf(s0 * v.x + h0, 0.f);
            xr[16 + b] = fmaxf(s1 * v.y + h1, 0.f);
            xr[32 + b] = fmaxf(s2 * v.z + h2, 0.f);
            xr[48 + b] = fmaxf(s3 * v.w + h3, 0.f);
        }
    }
    __syncthreads();
    unsigned long long acc[32];           // acc[j(4)][b-pair(8)]
#pragma unroll
    for (int i = 0; i < 32; i++) acc[i] = 0ULL;
    int j0 = t * 4;
#pragma unroll 1
    for (int c = 0; c < NCHUNK; c++) {
        int s = c & (NST - 1);
        int par = (c >> 2) & 1;           // completion-phase parity for NST=4
        MBARRIER_WAIT_PARITY(mb0 + 8 * s, par);
        const float* wst = ws[s];
#pragma unroll
        for (int i = 0; i < SROWS; i++) {
            float4 wv = *(const float4*)(wst + i * FW + j0);
            FC1_STEP(wv, c * SROWS + i);
        }
        __syncthreads();                  // all reads of ws[s] done
        int nc = c + NST;
        if (t == 0 && nc < NCHUNK) {      // refill stage s with chunk nc
            MBARRIER_EXPECT_TX(mb0 + 8 * s, STB);
            BULK_G2S(ws0 + s * STB, wsrc + (size_t)nc * STB, STB, mb0 + 8 * s);
        }
    }
    float* pbase = g_part + (size_t)ck * BSZ * FW + j0;
#pragma unroll
    for (int bp = 0; bp < 8; bp++) {      // b-pair bp -> rows 2bp, 2bp+1
        float lo0, hi0, lo1, hi1, lo2, hi2, lo3, hi3;
        UNPACKD(lo0, hi0, acc[0 * 8 + bp]);
        UNPACKD(lo1, hi1, acc[1 * 8 + bp]);
        UNPACKD(lo2, hi2, acc[2 * 8 + bp]);
        UNPACKD(lo3, hi3, acc[3 * 8 + bp]);
        float4 e = {lo0, lo1, lo2, lo3};
        float4 o = {hi0, hi1, hi2, hi3};
        *(float4*)(pbase + (size_t)(2 * bp + 0) * FW) = e;
        *(float4*)(pbase + (size_t)(2 * bp + 1) * FW) = o;
    }
}

// ================= reduce partials (stage 1, coalesced float4) ============
__global__ void k_red1() {
    int b = blockIdx.x >> 3;             // 0..15
    int grp = blockIdx.x & 7;            // 0..7, each covers 64 chunks
    int t = threadIdx.x;                 // 128 threads, j-quad each
    const float* p = g_part + (size_t)(grp * 64) * BSZ * FW + (size_t)b * FW + t * 4;
    float4 s = {0, 0, 0, 0};
#pragma unroll 8
    for (int k = 0; k < 64; k++) {
        float4 v = *(const float4*)(p + (size_t)k * BSZ * FW);
        s.x += v.x; s.y += v.y; s.z += v.z; s.w += v.w;
    }
    *(float4*)(g_red + (size_t)(b * 8 + grp) * FW + t * 4) = s;
}

// ================= final: reduce + extras + bias + relu + fc2 =============
__global__ void k_red2(const float* __restrict__ w, const float* __restrict__ fc1b,
                       const float* __restrict__ ex, const float* __restrict__ fc2w,
                       const float* __restrict__ fc2b, float* __restrict__ out) {
    int b = blockIdx.x;                  // 16 blocks
    int j = threadIdx.x;                 // 512 threads
    float acc = fc1b[j];
#pragma unroll
    for (int g = 0; g < 8; g++) acc += g_red[(size_t)(b * 8 + g) * FW + j];
#pragma unroll
    for (int e2 = 0; e2 < 32; e2++)
        acc += ex[b * 32 + e2] * w[((size_t)KTOT + e2) * FW + j];
    float h = fmaxf(acc, 0.f);
    __shared__ float r0[512], r1[512];
    r0[j] = h * fc2w[j * 2 + 0];
    r1[j] = h * fc2w[j * 2 + 1];
    __syncthreads();
    for (int s = 256; s > 0; s >>= 1) {
        if (j < s) { r0[j] += r0[j + s]; r1[j] += r1[j + s]; }
        __syncthreads();
    }
    if (j == 0) {
        out[b * 2 + 0] = r0[0] + fc2b[0];
        out[b * 2 + 1] = r1[0] + fc2b[1];
    }
}

// ================= launch ==================================================
extern "C" void kernel_launch(void* const* d_in, const int* in_sizes, int n_in,
                              void* d_out, int out_size) {
    const float* inputs  = (const float*)d_in[0];
    const float* ex      = (const float*)d_in[1];
    const int*   erow    = (const int*)  d_in[2];
    const int*   ecol    = (const int*)  d_in[3];
    const float* eval    = (const float*)d_in[4];
    const float* W1      = (const float*)d_in[5];
    const float* b1      = (const float*)d_in[6];
    const float* g1      = (const float*)d_in[7];
    const float* be1     = (const float*)d_in[8];
    const float* W2      = (const float*)d_in[9];
    const float* b2      = (const float*)d_in[10];
    const float* g2      = (const float*)d_in[11];
    const float* be2     = (const float*)d_in[12];
    const float* fc1w    = (const float*)d_in[13];
    const float* fc1b    = (const float*)d_in[14];
    const float* fc2w    = (const float*)d_in[15];
    const float* fc2b    = (const float*)d_in[16];
    float* out = (float*)d_out;

    float* bufA; cudaGetSymbolAddress((void**)&bufA, g_bufA);
    float* bufB; cudaGetSymbolAddress((void**)&bufB, g_bufB);
    int* cnt;    cudaGetSymbolAddress((void**)&cnt,  g_count);

    // Kernel order: spmm is the 4th kernel launch -> profiled by ncu.
    cudaMemsetAsync(cnt, 0, MM * sizeof(int));
    k_histscan<<<NNZ / 1024, 256>>>(erow);                  // k1: hist+scan fused
    k_lin1<<<MM / 16, 256>>>(inputs, W1);                   // k2: bufA = X@W1
    k_scatter<<<NNZ / 1024, 256>>>(erow, ecol, eval);       // k3
    k_spmm<<<MM, 128>>>(bufA, b1, bufB);                    // k4 (profiled)
    k_bn<<<64, 256>>>(g1, be1);
    k_lin2<<<(BSZ * MM) / 256, 256>>>(bufB, W2, bufA);      // bufA = bnrelu(bufB)@W2
    k_spmm<<<MM, 128>>>(bufA, b2, bufB);                    // bufB = L@bufA + b2
    k_bn<<<64, 256>>>(g2, be2);

    k_fc1<<<NKCH, 128>>>(fc1w, bufB);                       // TMA-pipelined split-K
    k_red1<<<BSZ * 8, 128>>>();                             // coalesced partial reduce
    k_red2<<<BSZ, 512>>>(fc1w, fc1b, ex, fc2w, fc2b, out);  // finish + fc2
}